// round 1
// baseline (speedup 1.0000x reference)
#include <cuda_runtime.h>

#define BATCH   4096
#define IN_DIM  4096
#define OUT_DIM 4096
#define BN_EPS  1e-3f

// Scratch (no device allocation allowed -> __device__ globals)
__device__ float g_sum[OUT_DIM];
__device__ float g_sumsq[OUT_DIM];
__device__ float g_scale[OUT_DIM];
__device__ float g_shift[OUT_DIM];

__global__ void zero_stats_kernel() {
    int i = blockIdx.x * blockDim.x + threadIdx.x;
    if (i < OUT_DIM) { g_sum[i] = 0.f; g_sumsq[i] = 0.f; }
}

// Pass 1: per-split block GEMM (64 rows x 64 cols per block), bias add,
// store pre-BN result to out, accumulate per-column sum / sumsq.
__global__ __launch_bounds__(128) void pass1_kernel(
    const float* __restrict__ x, const float* __restrict__ w,
    const float* __restrict__ bias, float* __restrict__ out)
{
    __shared__ float Xs[64][65];   // +1 pad: conflict-free column reads
    __shared__ float Ws[64][64];
    __shared__ float s_sum[64];
    __shared__ float s_sq[64];

    const int s       = blockIdx.y;        // split 0..63
    const int rowBase = blockIdx.x * 64;   // batch tile
    const int tid     = threadIdx.x;

    if (tid < 64) { s_sum[tid] = 0.f; s_sq[tid] = 0.f; }

    // Load W block: rows s*64..s*64+63, cols s*64..s*64+63 (block-diagonal)
    #pragma unroll
    for (int t = 0; t < 8; t++) {
        int idx = t * 128 + tid;           // 0..1023 float4s
        int i  = idx >> 4;
        int j4 = idx & 15;
        float4 v = *(const float4*)(w + (size_t)(s * 64 + i) * OUT_DIM + s * 64 + j4 * 4);
        *(float4*)(&Ws[i][j4 * 4]) = v;
    }
    // Load X tile: 64 rows x 64 cols of this split
    #pragma unroll
    for (int t = 0; t < 8; t++) {
        int idx = t * 128 + tid;
        int r  = idx >> 4;
        int j4 = idx & 15;
        float4 v = *(const float4*)(x + (size_t)(rowBase + r) * IN_DIM + s * 64 + j4 * 4);
        Xs[r][j4 * 4 + 0] = v.x;
        Xs[r][j4 * 4 + 1] = v.y;
        Xs[r][j4 * 4 + 2] = v.z;
        Xs[r][j4 * 4 + 3] = v.w;
    }
    __syncthreads();

    // Microtile: 4 rows x 8 cols per thread. 16x8 thread grid.
    const int tx = tid & 7;
    const int ty = tid >> 3;
    const int r0 = ty * 4;
    const int c0 = tx * 8;

    float acc[4][8];
    #pragma unroll
    for (int u = 0; u < 4; u++)
        #pragma unroll
        for (int v = 0; v < 8; v++)
            acc[u][v] = 0.f;

    #pragma unroll 8
    for (int k = 0; k < 64; k++) {
        float4 b0 = *(const float4*)(&Ws[k][c0]);
        float4 b1 = *(const float4*)(&Ws[k][c0 + 4]);
        float bb[8] = {b0.x, b0.y, b0.z, b0.w, b1.x, b1.y, b1.z, b1.w};
        float aa[4];
        #pragma unroll
        for (int u = 0; u < 4; u++) aa[u] = Xs[r0 + u][k];
        #pragma unroll
        for (int u = 0; u < 4; u++)
            #pragma unroll
            for (int v = 0; v < 8; v++)
                acc[u][v] = fmaf(aa[u], bb[v], acc[u][v]);
    }

    // Epilogue: bias, store pre-BN, column partial stats
    float bv[8];
    #pragma unroll
    for (int v = 0; v < 8; v++) bv[v] = __ldg(bias + s * 64 + c0 + v);

    float csum[8], csq[8];
    #pragma unroll
    for (int v = 0; v < 8; v++) { csum[v] = 0.f; csq[v] = 0.f; }

    #pragma unroll
    for (int u = 0; u < 4; u++) {
        float vals[8];
        #pragma unroll
        for (int v = 0; v < 8; v++) {
            float val = acc[u][v] + bv[v];
            vals[v] = val;
            csum[v] += val;
            csq[v]  = fmaf(val, val, csq[v]);
        }
        float* dst = out + (size_t)(rowBase + r0 + u) * OUT_DIM + s * 64 + c0;
        *(float4*)(dst + 0) = make_float4(vals[0], vals[1], vals[2], vals[3]);
        *(float4*)(dst + 4) = make_float4(vals[4], vals[5], vals[6], vals[7]);
    }

    #pragma unroll
    for (int v = 0; v < 8; v++) {
        atomicAdd(&s_sum[c0 + v], csum[v]);
        atomicAdd(&s_sq[c0 + v],  csq[v]);
    }
    __syncthreads();

    if (tid < 64) {
        atomicAdd(&g_sum[s * 64 + tid],   s_sum[tid]);
        atomicAdd(&g_sumsq[s * 64 + tid], s_sq[tid]);
    }
}

// Fold BN stats + gamma/beta into per-column scale & shift
__global__ void finalize_kernel(const float* __restrict__ gamma,
                                const float* __restrict__ beta) {
    int j = blockIdx.x * blockDim.x + threadIdx.x;
    if (j < OUT_DIM) {
        const float invB = 1.0f / (float)BATCH;
        float mean = g_sum[j] * invB;
        float var  = fmaxf(g_sumsq[j] * invB - mean * mean, 0.f);
        float sc   = gamma[j] * rsqrtf(var + BN_EPS);
        g_scale[j] = sc;
        g_shift[j] = fmaf(-mean, sc, beta[j]);
    }
}

// Pass 2: in-place normalize + ReLU, float4 vectorized
__global__ __launch_bounds__(256) void pass2_kernel(float* __restrict__ out) {
    int idx = blockIdx.x * blockDim.x + threadIdx.x;   // float4 index
    int j4  = idx & (OUT_DIM / 4 - 1);
    float4 v  = ((const float4*)out)[idx];
    float4 sc = ((const float4*)g_scale)[j4];
    float4 sh = ((const float4*)g_shift)[j4];
    v.x = fmaxf(fmaf(v.x, sc.x, sh.x), 0.f);
    v.y = fmaxf(fmaf(v.y, sc.y, sh.y), 0.f);
    v.z = fmaxf(fmaf(v.z, sc.z, sh.z), 0.f);
    v.w = fmaxf(fmaf(v.w, sc.w, sh.w), 0.f);
    ((float4*)out)[idx] = v;
}

extern "C" void kernel_launch(void* const* d_in, const int* in_sizes, int n_in,
                              void* d_out, int out_size) {
    const float* x     = (const float*)d_in[0];
    const float* w     = (const float*)d_in[1];
    const float* bias  = (const float*)d_in[2];
    const float* gamma = (const float*)d_in[3];
    const float* beta  = (const float*)d_in[4];
    float* out = (float*)d_out;

    zero_stats_kernel<<<16, 256>>>();
    pass1_kernel<<<dim3(BATCH / 64, 64), 128>>>(x, w, bias, out);
    finalize_kernel<<<16, 256>>>(gamma, beta);
    pass2_kernel<<<(BATCH * OUT_DIM / 4) / 256, 256>>>(out);
}

// round 3
// speedup vs baseline: 2.3317x; 2.3317x over previous
#include <cuda_runtime.h>
#include <cstdint>

#define BATCH   4096
#define IN_DIM  4096
#define OUT_DIM 4096
#define BN_EPS  1e-3f

#define XS_STRIDE 68   // words; bank = 4*gid + tig -> conflict-free A frags
#define BS_STRIDE 72   // words; bank = 8*tig + gid -> conflict-free B frags

// SMEM (dynamic): Xs[128][68] u32 | Bs[64][72] u32 | bias_s[64] f32
#define XS_OFF   0
#define BS_OFF   (128 * XS_STRIDE * 4)                 // 34816
#define BIAS_OFF (BS_OFF + 64 * BS_STRIDE * 4)         // 53248
#define SMEM_TOTAL (BIAS_OFF + 64 * 4)                 // 53504

// ---------------- scratch ---------------------------------------------------
__device__ float g_sum[OUT_DIM];
__device__ float g_sumsq[OUT_DIM];
__device__ float g_scale[OUT_DIM];
__device__ float g_shift[OUT_DIM];

__device__ __forceinline__ uint32_t f2tf32(float f) {
    uint32_t r;
    asm("cvt.rna.tf32.f32 %0, %1;" : "=r"(r) : "f"(f));
    return r;
}

__device__ __forceinline__ void mma_tf32(float c[4], const uint32_t a[4],
                                         const uint32_t b[2]) {
    asm volatile(
        "mma.sync.aligned.m16n8k8.row.col.f32.tf32.tf32.f32 "
        "{%0,%1,%2,%3}, {%4,%5,%6,%7}, {%8,%9}, {%0,%1,%2,%3};"
        : "+f"(c[0]), "+f"(c[1]), "+f"(c[2]), "+f"(c[3])
        : "r"(a[0]), "r"(a[1]), "r"(a[2]), "r"(a[3]), "r"(b[0]), "r"(b[1]));
}

// ---------------- kernels ---------------------------------------------------
__global__ void zero_stats_kernel() {
    int i = blockIdx.x * blockDim.x + threadIdx.x;
    if (i < OUT_DIM) { g_sum[i] = 0.f; g_sumsq[i] = 0.f; }
}

__global__ __launch_bounds__(128) void gemm_stats_kernel(
    const float* __restrict__ x, const float* __restrict__ w,
    const float* __restrict__ bias, float* __restrict__ out)
{
    extern __shared__ char smem[];
    uint32_t* Xs = (uint32_t*)(smem + XS_OFF);   // [128][XS_STRIDE]
    uint32_t* Bs = (uint32_t*)(smem + BS_OFF);   // [64][BS_STRIDE]
    float* bias_s = (float*)(smem + BIAS_OFF);

    const int tid  = threadIdx.x;
    const int wid  = tid >> 5;
    const int lane = tid & 31;
    const int gid  = lane >> 2;    // 0..7
    const int tig  = lane & 3;     // 0..3
    const int s       = blockIdx.y;
    const int rowBase = blockIdx.x * 128;

    // ---- load X tile [128 x 64] (cvt to tf32) ----
    #pragma unroll
    for (int i = 0; i < 16; i++) {
        int idx = i * 128 + tid;       // 0..2047 float4s
        int row = idx >> 4;
        int c4  = idx & 15;
        float4 v = *(const float4*)(x + (size_t)(rowBase + row) * IN_DIM + s * 64 + c4 * 4);
        uint32_t* d = Xs + row * XS_STRIDE + c4 * 4;
        d[0] = f2tf32(v.x); d[1] = f2tf32(v.y); d[2] = f2tf32(v.z); d[3] = f2tf32(v.w);
    }
    // ---- load W block as Bs[k][n] = w[s*64+k][s*64+n] ----
    #pragma unroll
    for (int i = 0; i < 8; i++) {
        int idx = i * 128 + tid;       // 0..1023 float4s
        int k  = idx >> 4;
        int c4 = idx & 15;
        float4 v = *(const float4*)(w + (size_t)(s * 64 + k) * OUT_DIM + s * 64 + c4 * 4);
        uint32_t* d = Bs + k * BS_STRIDE + c4 * 4;
        d[0] = f2tf32(v.x); d[1] = f2tf32(v.y); d[2] = f2tf32(v.z); d[3] = f2tf32(v.w);
    }
    if (tid < 16) {
        float4 v = *(const float4*)(bias + s * 64 + tid * 4);
        *(float4*)(bias_s + tid * 4) = v;
    }
    __syncthreads();

    // ---- tensor-core mainloop: warp = 32 rows x 64 cols ----
    float c[2][8][4];
    #pragma unroll
    for (int mc = 0; mc < 2; mc++)
        #pragma unroll
        for (int nc = 0; nc < 8; nc++)
            #pragma unroll
            for (int q = 0; q < 4; q++)
                c[mc][nc][q] = 0.f;

    #pragma unroll
    for (int kc = 0; kc < 8; kc++) {
        const int k0 = kc * 8;
        uint32_t a[2][4];
        #pragma unroll
        for (int mc = 0; mc < 2; mc++) {
            int r = wid * 32 + mc * 16 + gid;
            a[mc][0] = Xs[r * XS_STRIDE + k0 + tig];
            a[mc][1] = Xs[(r + 8) * XS_STRIDE + k0 + tig];
            a[mc][2] = Xs[r * XS_STRIDE + k0 + tig + 4];
            a[mc][3] = Xs[(r + 8) * XS_STRIDE + k0 + tig + 4];
        }
        uint32_t b[8][2];
        #pragma unroll
        for (int nc = 0; nc < 8; nc++) {
            b[nc][0] = Bs[(k0 + tig) * BS_STRIDE + nc * 8 + gid];
            b[nc][1] = Bs[(k0 + tig + 4) * BS_STRIDE + nc * 8 + gid];
        }
        #pragma unroll
        for (int mc = 0; mc < 2; mc++)
            #pragma unroll
            for (int nc = 0; nc < 8; nc++)
                mma_tf32(c[mc][nc], a[mc], b[nc]);
    }
    __syncthreads();   // done reading Xs/Bs; about to overwrite as stage

    // ---- bias add + stage to SMEM (reuse Xs region, stride 68) ----
    float* stage = (float*)(smem + XS_OFF);
    #pragma unroll
    for (int mc = 0; mc < 2; mc++) {
        int r = wid * 32 + mc * 16 + gid;
        #pragma unroll
        for (int nc = 0; nc < 8; nc++) {
            int col = nc * 8 + 2 * tig;
            float bx = bias_s[col], by = bias_s[col + 1];
            stage[r * XS_STRIDE + col]           = c[mc][nc][0] + bx;
            stage[r * XS_STRIDE + col + 1]       = c[mc][nc][1] + by;
            stage[(r + 8) * XS_STRIDE + col]     = c[mc][nc][2] + bx;
            stage[(r + 8) * XS_STRIDE + col + 1] = c[mc][nc][3] + by;
        }
    }
    __syncthreads();

    // ---- coalesced store of pre-BN tile ----
    #pragma unroll
    for (int i = 0; i < 16; i++) {
        int idx = i * 128 + tid;
        int row = idx >> 4;
        int c4  = idx & 15;
        float4 v = *(const float4*)(stage + row * XS_STRIDE + c4 * 4);
        *(float4*)(out + (size_t)(rowBase + row) * OUT_DIM + s * 64 + c4 * 4) = v;
    }
    // ---- per-column partial stats ----
    {
        const int j = tid & 63;
        const int half = tid >> 6;
        float sm = 0.f, sq = 0.f;
        #pragma unroll 8
        for (int rr = 0; rr < 64; rr++) {
            float v = stage[(half * 64 + rr) * XS_STRIDE + j];
            sm += v;
            sq = fmaf(v, v, sq);
        }
        atomicAdd(&g_sum[s * 64 + j], sm);
        atomicAdd(&g_sumsq[s * 64 + j], sq);
    }
}

__global__ void finalize_kernel(const float* __restrict__ gamma,
                                const float* __restrict__ beta) {
    int j = blockIdx.x * blockDim.x + threadIdx.x;
    if (j < OUT_DIM) {
        const float invB = 1.0f / (float)BATCH;
        float mean = g_sum[j] * invB;
        float var  = fmaxf(g_sumsq[j] * invB - mean * mean, 0.f);
        float sc   = gamma[j] * rsqrtf(var + BN_EPS);
        g_scale[j] = sc;
        g_shift[j] = fmaf(-mean, sc, beta[j]);
    }
}

__global__ __launch_bounds__(256) void pass2_kernel(float* __restrict__ out) {
    int idx = blockIdx.x * blockDim.x + threadIdx.x;   // float4 index
    int j4  = idx & (OUT_DIM / 4 - 1);
    float4 v  = ((const float4*)out)[idx];
    float4 sc = ((const float4*)g_scale)[j4];
    float4 sh = ((const float4*)g_shift)[j4];
    v.x = fmaxf(fmaf(v.x, sc.x, sh.x), 0.f);
    v.y = fmaxf(fmaf(v.y, sc.y, sh.y), 0.f);
    v.z = fmaxf(fmaf(v.z, sc.z, sh.z), 0.f);
    v.w = fmaxf(fmaf(v.w, sc.w, sh.w), 0.f);
    ((float4*)out)[idx] = v;
}

extern "C" void kernel_launch(void* const* d_in, const int* in_sizes, int n_in,
                              void* d_out, int out_size) {
    const float* x     = (const float*)d_in[0];
    const float* w     = (const float*)d_in[1];
    const float* bias  = (const float*)d_in[2];
    const float* gamma = (const float*)d_in[3];
    const float* beta  = (const float*)d_in[4];
    float* out = (float*)d_out;

    static bool attr_set = false;
    if (!attr_set) {
        cudaFuncSetAttribute(gemm_stats_kernel,
                             cudaFuncAttributeMaxDynamicSharedMemorySize, SMEM_TOTAL);
        attr_set = true;
    }

    zero_stats_kernel<<<16, 256>>>();
    gemm_stats_kernel<<<dim3(BATCH / 128, 64), 128, SMEM_TOTAL>>>(x, w, bias, out);
    finalize_kernel<<<16, 256>>>(gamma, beta);
    pass2_kernel<<<(BATCH * OUT_DIM / 4) / 256, 256>>>(out);
}